// round 5
// baseline (speedup 1.0000x reference)
#include <cuda_runtime.h>

#define B_   1024
#define D_   1024
#define F_   32768
#define L0   32
#define NMAX 33

// ---------------- persistent state (device globals; no allocation) ----------------
__device__ float              g_resid[B_ * D_];     // residual per row (4 MB)
__device__ float              g_w[B_ * NMAX];       // sparse weights
__device__ int                g_idx[B_ * NMAX];     // sparse indices
__device__ int                g_nnz[B_];            // active count per row
__device__ unsigned long long g_amax[B_];           // packed (ordered_val<<32 | ~idx)

__device__ __forceinline__ unsigned ordf(float v) {
    unsigned u = __float_as_uint(v);
    return (u & 0x80000000u) ? ~u : (u | 0x80000000u);
}

// ---------------- init: residual = x, nnz = 0, amax = 0 ----------------
__global__ void k_init(const float* __restrict__ x) {
    int i = blockIdx.x * blockDim.x + threadIdx.x;
    if (i < B_ * D_) g_resid[i] = x[i];
    if (i < B_) { g_nnz[i] = 0; g_amax[i] = 0ULL; }
}

// ---------------- GEMM + argmax:  ip[b,f] = <resid_b, xs_f>, reduce argmax_f ------
// tile 128(b) x 128(f), 256 threads, 8x8 per thread, K staged 16 at a time,
// f32x2 packed FMA along K (even/odd partial sums, horizontal add at end).
#define LDT 18  // padded smem row stride (floats): conflict-free LDS.64

__global__ __launch_bounds__(256, 1) void k_gemm(const float* __restrict__ xs) {
    __shared__ float sA[2][128 * LDT];
    __shared__ float sB[2][128 * LDT];

    const int tid = threadIdx.x;
    const int tx = tid & 15;          // f direction
    const int ty = tid >> 4;          // b direction
    const int b0 = blockIdx.x * 128;  // b tiles fastest -> XS reuse in L2
    const int f0 = blockIdx.y * 128;

    const int lrow = tid >> 1;        // 0..127
    const int lcol = (tid & 1) * 8;   // 0 or 8
    const float* Ag = g_resid + (size_t)(b0 + lrow) * D_ + lcol;
    const float* Bg = xs      + (size_t)(f0 + lrow) * D_ + lcol;

    unsigned long long acc[8][8];
#pragma unroll
    for (int i = 0; i < 8; i++)
#pragma unroll
        for (int j = 0; j < 8; j++) acc[i][j] = 0ULL;

    float4 ra0, ra1, rb0, rb1;
    ra0 = *(const float4*)(Ag);
    ra1 = *(const float4*)(Ag + 4);
    rb0 = *(const float4*)(Bg);
    rb1 = *(const float4*)(Bg + 4);
    {
        float* pa = &sA[0][lrow * LDT + lcol];
        pa[0] = ra0.x; pa[1] = ra0.y; pa[2] = ra0.z; pa[3] = ra0.w;
        pa[4] = ra1.x; pa[5] = ra1.y; pa[6] = ra1.z; pa[7] = ra1.w;
        float* pb = &sB[0][lrow * LDT + lcol];
        pb[0] = rb0.x; pb[1] = rb0.y; pb[2] = rb0.z; pb[3] = rb0.w;
        pb[4] = rb1.x; pb[5] = rb1.y; pb[6] = rb1.z; pb[7] = rb1.w;
    }
    __syncthreads();

#pragma unroll 1
    for (int s = 0; s < 64; s++) {
        const int cur = s & 1;
        if (s < 63) {
            const float* Ag2 = Ag + (s + 1) * 16;
            const float* Bg2 = Bg + (s + 1) * 16;
            ra0 = *(const float4*)(Ag2);
            ra1 = *(const float4*)(Ag2 + 4);
            rb0 = *(const float4*)(Bg2);
            rb1 = *(const float4*)(Bg2 + 4);
        }
        const float* a   = &sA[cur][ty * 8 * LDT];
        const float* bsh = &sB[cur][tx * LDT];
#pragma unroll
        for (int kp = 0; kp < 8; kp++) {
            unsigned long long a2[8], b2[8];
#pragma unroll
            for (int i = 0; i < 8; i++)
                a2[i] = *(const unsigned long long*)(a + i * LDT + kp * 2);
#pragma unroll
            for (int j = 0; j < 8; j++)
                b2[j] = *(const unsigned long long*)(bsh + j * 16 * LDT + kp * 2);
#pragma unroll
            for (int i = 0; i < 8; i++)
#pragma unroll
                for (int j = 0; j < 8; j++)
                    asm("fma.rn.f32x2 %0, %1, %2, %0;"
                        : "+l"(acc[i][j]) : "l"(a2[i]), "l"(b2[j]));
        }
        if (s < 63) {
            const int nxt = cur ^ 1;
            float* pa = &sA[nxt][lrow * LDT + lcol];
            pa[0] = ra0.x; pa[1] = ra0.y; pa[2] = ra0.z; pa[3] = ra0.w;
            pa[4] = ra1.x; pa[5] = ra1.y; pa[6] = ra1.z; pa[7] = ra1.w;
            float* pb = &sB[nxt][lrow * LDT + lcol];
            pb[0] = rb0.x; pb[1] = rb0.y; pb[2] = rb0.z; pb[3] = rb0.w;
            pb[4] = rb1.x; pb[5] = rb1.y; pb[6] = rb1.z; pb[7] = rb1.w;
            __syncthreads();
        }
    }

    // epilogue: per-row argmax with first-max tie-break
#pragma unroll
    for (int i = 0; i < 8; i++) {
        const int bb = b0 + ty * 8 + i;
        float best = -3.402823466e+38f;
        int bestf = f0 + tx;  // smallest f this thread owns
#pragma unroll
        for (int j = 0; j < 8; j++) {
            float lo = __uint_as_float((unsigned)acc[i][j]);
            float hi = __uint_as_float((unsigned)(acc[i][j] >> 32));
            float v = lo + hi;
            int f = f0 + j * 16 + tx;  // f ascends with j -> strict > keeps first max
            if (v > best) { best = v; bestf = f; }
        }
        unsigned long long key =
            ((unsigned long long)ordf(best) << 32) | (unsigned)(~(unsigned)bestf);
#pragma unroll
        for (int off = 8; off; off >>= 1) {
            unsigned long long o = __shfl_down_sync(0xffffffffu, key, off, 16);
            if (o > key) key = o;
        }
        if (tx == 0) atomicMax(&g_amax[bb], key);
    }
}

// ---------------- per-row sparse update (one block per row) ----------------
// smem: residual (1024) + up to 33 atom rows (33*1024) = 34*1024 floats
__global__ __launch_bounds__(256) void k_upd(const float* __restrict__ x,
                                             const float* __restrict__ xs) {
    extern __shared__ float dsm[];
    float* rsm   = dsm;        // [1024]
    float* atoms = dsm + D_;   // [NMAX][1024]

    __shared__ int   ilist[NMAX];
    __shared__ float wlist[NMAX];
    __shared__ float gsm[NMAX];
    __shared__ int   sh_n;
    __shared__ float sh_step;
    __shared__ float redn[8], redd[8];

    const int b = blockIdx.x;
    const int tid = threadIdx.x;

    int n = g_nnz[b];
    if (tid < n) {
        ilist[tid] = g_idx[b * NMAX + tid];
        wlist[tid] = g_w[b * NMAX + tid];
    }
    __syncthreads();
    if (tid == 0) {
        unsigned long long key = g_amax[b];
        int m = (int)(~(unsigned)key);
        bool found = false;
        for (int j = 0; j < n; j++)
            if (ilist[j] == m) { found = true; break; }
        if (!found) { ilist[n] = m; wlist[n] = 0.f; n++; }
        sh_n = n;
        g_amax[b] = 0ULL;  // reset for next iteration
    }
    __syncthreads();
    n = sh_n;

    for (int v = tid; v < D_; v += 256) rsm[v] = g_resid[(size_t)b * D_ + v];
    for (int e = tid; e < n * D_; e += 256) {
        int j = e >> 10, v = e & (D_ - 1);
        atoms[j * D_ + v] = xs[(size_t)ilist[j] * D_ + v];
    }
    __syncthreads();

    // grads: one warp per atom  g_j = <r, a_j>
    const int wid = tid >> 5, lane = tid & 31;
    for (int j = wid; j < n; j += 8) {
        float s = 0.f;
        const float* a = atoms + j * D_;
        for (int v = lane; v < D_; v += 32) s += rsm[v] * a[v];
#pragma unroll
        for (int off = 16; off; off >>= 1) s += __shfl_down_sync(0xffffffffu, s, off);
        if (lane == 0) gsm[j] = s;
    }
    __syncthreads();

    // c = sum_j g_j a_j; num = <c,r>; den = <c,c>
    float num = 0.f, den = 0.f;
    {
        const int v0 = tid * 4;
        float c0 = 0.f, c1 = 0.f, c2 = 0.f, c3 = 0.f;
        for (int j = 0; j < n; j++) {
            float g = gsm[j];
            const float* a = atoms + j * D_ + v0;
            c0 += g * a[0]; c1 += g * a[1]; c2 += g * a[2]; c3 += g * a[3];
        }
        num = c0 * rsm[v0] + c1 * rsm[v0 + 1] + c2 * rsm[v0 + 2] + c3 * rsm[v0 + 3];
        den = c0 * c0 + c1 * c1 + c2 * c2 + c3 * c3;
    }
#pragma unroll
    for (int off = 16; off; off >>= 1) {
        num += __shfl_down_sync(0xffffffffu, num, off);
        den += __shfl_down_sync(0xffffffffu, den, off);
    }
    if (lane == 0) { redn[wid] = num; redd[wid] = den; }
    __syncthreads();
    if (tid == 0) {
        float N = 0.f, De = 0.f;
        for (int w = 0; w < 8; w++) { N += redn[w]; De += redd[w]; }
        sh_step = N / fmaxf(De, 1e-3f);
    }
    __syncthreads();
    const float step = sh_step;

    if (tid < n) wlist[tid] = fmaxf(0.f, wlist[tid] + step * gsm[tid]);
    __syncthreads();

    // new residual r = x - sum_j w_j a_j  (w==0 terms contribute exact 0)
    for (int v = tid; v < D_; v += 256) {
        float r = x[(size_t)b * D_ + v];
        for (int j = 0; j < n; j++) r -= wlist[j] * atoms[j * D_ + v];
        g_resid[(size_t)b * D_ + v] = r;
    }

    if (tid == 0) {  // compact (keep w > 0)
        int nn = 0;
        for (int j = 0; j < n; j++)
            if (wlist[j] > 0.f) {
                g_idx[b * NMAX + nn] = ilist[j];
                g_w[b * NMAX + nn] = wlist[j];
                nn++;
            }
        g_nnz[b] = nn;
    }
}

// ---------------- finalize: top_k emulation, decode, loss ----------------
__global__ __launch_bounds__(256) void k_fin(const float* __restrict__ y,
                                             const float* __restrict__ xs,
                                             const float* __restrict__ ys,
                                             float* __restrict__ out) {
    const int b = blockIdx.x, tid = threadIdx.x;
    __shared__ float sw[L0];
    __shared__ int   si[L0];
    __shared__ int   sn;
    __shared__ float red[8];

    if (tid == 0) {
        int n = g_nnz[b];
        float w[NMAX]; int id[NMAX];
        for (int j = 0; j < n; j++) { w[j] = g_w[b * NMAX + j]; id[j] = g_idx[b * NMAX + j]; }
        // stable sort: value desc, index asc on ties (matches lax.top_k)
        for (int a = 1; a < n; a++) {
            float wv = w[a]; int iv = id[a]; int p = a - 1;
            while (p >= 0 && (w[p] < wv || (w[p] == wv && id[p] > iv))) {
                w[p + 1] = w[p]; id[p + 1] = id[p]; p--;
            }
            w[p + 1] = wv; id[p + 1] = iv;
        }
        for (int k = 0; k < n; k++) { sw[k] = w[k]; si[k] = id[k]; }
        // pad with smallest indices whose weight is zero (not in support)
        int f = 0;
        for (int k = n; k < L0; k++) {
            for (;;) {
                bool inS = false;
                for (int j = 0; j < n; j++) if (id[j] == f) { inS = true; break; }
                if (!inS) break;
                f++;
            }
            si[k] = f; sw[k] = 0.f; f++;
        }
        sn = n;
    }
    __syncthreads();
    const int n = sn;

    const size_t OFF_I  = (size_t)B_ * L0;
    const size_t OFF_XR = 2 * (size_t)B_ * L0;
    const size_t OFF_YR = OFF_XR + (size_t)B_ * D_;
    const size_t OFF_L  = OFF_YR + (size_t)B_ * D_;

    if (tid < L0) {
        out[(size_t)b * L0 + tid] = sw[tid];
        out[OFF_I + (size_t)b * L0 + tid] = (float)si[tid];
    }

    float lsum = 0.f;
    for (int v = tid; v < D_; v += 256) {
        float xr = 0.f, yr = 0.f;
        for (int k = 0; k < n; k++) {
            float w = sw[k];
            size_t base = (size_t)si[k] * D_ + v;
            xr += w * xs[base];
            yr += w * ys[base];
        }
        out[OFF_XR + (size_t)b * D_ + v] = xr;
        out[OFF_YR + (size_t)b * D_ + v] = yr;
        float d = yr - y[(size_t)b * D_ + v];
        lsum += d * d;
    }
    const int wid = tid >> 5, lane = tid & 31;
#pragma unroll
    for (int off = 16; off; off >>= 1) lsum += __shfl_down_sync(0xffffffffu, lsum, off);
    if (lane == 0) red[wid] = lsum;
    __syncthreads();
    if (tid == 0) {
        float L = 0.f;
        for (int w = 0; w < 8; w++) L += red[w];
        out[OFF_L + b] = L;
    }
}

// ---------------- launch ----------------
extern "C" void kernel_launch(void* const* d_in, const int* in_sizes, int n_in,
                              void* d_out, int out_size) {
    const float* x  = (const float*)d_in[0];
    const float* y  = (const float*)d_in[1];
    const float* xs = (const float*)d_in[2];
    const float* ys = (const float*)d_in[3];
    float* out = (float*)d_out;

    cudaFuncSetAttribute(k_upd, cudaFuncAttributeMaxDynamicSharedMemorySize,
                         (1 + NMAX) * D_ * (int)sizeof(float));

    k_init<<<(B_ * D_ + 255) / 256, 256>>>(x);
    for (int t = 0; t < L0; t++) {
        k_gemm<<<dim3(B_ / 128, F_ / 128), 256>>>(xs);
        k_upd<<<B_, 256, (1 + NMAX) * D_ * (int)sizeof(float)>>>(x, xs);
    }
    k_fin<<<B_, 256>>>(y, xs, ys, out);
}

// round 11
// speedup vs baseline: 1.3699x; 1.3699x over previous
#include <cuda_runtime.h>
#include <cuda_bf16.h>

#define B_   1024
#define D_   1024
#define F_   32768
#define L0   32
#define NMAX 33

// bf16 3-way split GEMM geometry
#define KCAT   6144          // 6 segments x 1024
#define NCHUNK 96            // KCAT / 64
#define MT     128
#define NT     256
#define ABYTES (MT * 128)    // 16384 (128 rows x 128B, one K64 chunk)
#define BBYTES (NT * 128)    // 32768 (256 rows x 128B)
#define STGB   (ABYTES + BBYTES)   // 49152
#define NSTG   4

// ---------------- persistent state (device globals; no allocation) ----------------
__device__ float              g_resid[B_ * D_];
__device__ float              g_w[B_ * NMAX];
__device__ int                g_idx[B_ * NMAX];
__device__ int                g_nnz[B_];
__device__ unsigned long long g_amax[B_];
// tiled + SW128-preswizzled bf16 operands
__device__ __align__(1024) unsigned char g_xscat[(size_t)(F_ / NT) * NCHUNK * BBYTES]; // 384 MB
__device__ __align__(1024) unsigned char g_rcat[(B_ / MT) * NCHUNK * ABYTES];          // 12 MB

__device__ __forceinline__ unsigned ordf(float v) {
    unsigned u = __float_as_uint(v);
    return (u & 0x80000000u) ? ~u : (u | 0x80000000u);
}

__device__ __forceinline__ unsigned smem_u32(const void* p) {
    unsigned a;
    asm("{ .reg .u64 t; cvta.to.shared.u64 t, %1; cvt.u32.u64 %0, t; }" : "=r"(a) : "l"(p));
    return a;
}

// ---------------- sm_80-level async-copy / ldmatrix / mma helpers ----------------
__device__ __forceinline__ void cpa16(unsigned dst, const void* src) {
    asm volatile("cp.async.cg.shared.global [%0], [%1], 16;" :: "r"(dst), "l"(src));
}
__device__ __forceinline__ void ldsm4(unsigned& r0, unsigned& r1, unsigned& r2, unsigned& r3,
                                      unsigned addr) {
    asm volatile("ldmatrix.sync.aligned.m8n8.x4.shared.b16 {%0,%1,%2,%3}, [%4];"
                 : "=r"(r0), "=r"(r1), "=r"(r2), "=r"(r3) : "r"(addr));
}
__device__ __forceinline__ void mma16816(float* c, const unsigned* a, unsigned b0, unsigned b1) {
    asm volatile("mma.sync.aligned.m16n8k16.row.col.f32.bf16.bf16.f32 "
                 "{%0,%1,%2,%3}, {%4,%5,%6,%7}, {%8,%9}, {%0,%1,%2,%3};"
                 : "+f"(c[0]), "+f"(c[1]), "+f"(c[2]), "+f"(c[3])
                 : "r"(a[0]), "r"(a[1]), "r"(a[2]), "r"(a[3]), "r"(b0), "r"(b1));
}

// ---------------- split helper: write one residual element into r_cat ----------------
// r segments: [h, h, m, h, l, m]  pair with xs segments [H, M, H, L, H, M]
__device__ __forceinline__ void store_rcat(int b, int d, float r) {
    __nv_bfloat16 h = __float2bfloat16(r);
    float hf = __bfloat162float(h);
    __nv_bfloat16 m = __float2bfloat16(r - hf);
    float mf = __bfloat162float(m);
    __nv_bfloat16 l = __float2bfloat16(r - hf - mf);
    const int bt = b >> 7, row = b & 127;
    const unsigned swz = (unsigned)((row & 7) << 4);
    __nv_bfloat16 vals[6] = {h, h, m, h, l, m};
#pragma unroll
    for (int seg = 0; seg < 6; seg++) {
        int kpos = seg * D_ + d;
        int kc = kpos >> 6, e = kpos & 63;
        size_t addr = (size_t)(bt * NCHUNK + kc) * ABYTES + row * 128 + (((unsigned)(e * 2)) ^ swz);
        *(__nv_bfloat16*)(g_rcat + addr) = vals[seg];
    }
}

// ---------------- prep xs_cat: tiled, segment-concatenated, pre-swizzled ----------------
__global__ void k_prep_xs(const float* __restrict__ xs) {
    const int f = blockIdx.x;
    const int kc = threadIdx.x >> 3, e8 = threadIdx.x & 7;
    const int seg = kc >> 4;
    const int d0 = (kc & 15) * 64 + e8 * 8;
    const float* src = xs + (size_t)f * D_ + d0;
    float4 a = *(const float4*)src;
    float4 b = *(const float4*)(src + 4);
    float xv[8] = {a.x, a.y, a.z, a.w, b.x, b.y, b.z, b.w};
    unsigned short us[8];
#pragma unroll
    for (int j = 0; j < 8; j++) {
        float x = xv[j];
        __nv_bfloat16 h = __float2bfloat16(x);
        float hf = __bfloat162float(h);
        __nv_bfloat16 v;
        if (seg == 0 || seg == 2 || seg == 4) v = h;                       // H
        else if (seg == 3) {                                               // L
            __nv_bfloat16 m = __float2bfloat16(x - hf);
            v = __float2bfloat16(x - hf - __bfloat162float(m));
        } else v = __float2bfloat16(x - hf);                               // M
        us[j] = *(unsigned short*)&v;
    }
    const int row = f & (NT - 1);
    size_t addr = (size_t)((f >> 8) * NCHUNK + kc) * BBYTES + row * 128 +
                  ((unsigned)((e8 ^ (row & 7)) << 4));
    uint4 val;
    val.x = us[0] | ((unsigned)us[1] << 16);
    val.y = us[2] | ((unsigned)us[3] << 16);
    val.z = us[4] | ((unsigned)us[5] << 16);
    val.w = us[6] | ((unsigned)us[7] << 16);
    *(uint4*)(g_xscat + addr) = val;
}

// ---------------- init ----------------
__global__ void k_init(const float* __restrict__ x) {
    int i = blockIdx.x * blockDim.x + threadIdx.x;
    if (i < B_ * D_) {
        float v = x[i];
        g_resid[i] = v;
        store_rcat(i >> 10, i & (D_ - 1), v);
    }
    if (i < B_) { g_nnz[i] = 0; g_amax[i] = 0ULL; }
}

// ---------------- HMMA GEMM + argmax ----------------
// grid (8, 128): blockIdx.x = b-tile (fastest -> xs tiles shared in L2), y = f-tile
__global__ __launch_bounds__(256, 1) void k_gemm_mma() {
    extern __shared__ unsigned char smem[];
    const int tid = threadIdx.x, wid = tid >> 5, l = tid & 31;
    const unsigned sb = smem_u32(smem);
    const unsigned char* gA = g_rcat  + (size_t)blockIdx.x * NCHUNK * ABYTES;
    const unsigned char* gB = g_xscat + (size_t)blockIdx.y * NCHUNK * BBYTES;

    const int wm = wid & 1, wn = wid >> 1;          // warp grid 2(M) x 4(N)
    // ldmatrix.x4 lane->row/kgroup mapping (canonical m16n8k16 fragments)
    const unsigned rowA = (unsigned)((l & 7) + ((l >> 3) & 1) * 8 + wm * 64);
    const unsigned kgA  = (unsigned)(l >> 4);
    const unsigned rowB = (unsigned)((l & 7) + ((l >> 4) & 1) * 8 + wn * 64);
    const unsigned kgB  = (unsigned)((l >> 3) & 1);
    const unsigned sw   = (unsigned)(l & 7);

    float acc[4][8][4];
#pragma unroll
    for (int i = 0; i < 4; i++)
#pragma unroll
        for (int j = 0; j < 8; j++)
#pragma unroll
            for (int k = 0; k < 4; k++) acc[i][j][k] = 0.f;

    auto issue = [&](int c) {
        const int st = c & (NSTG - 1);
        unsigned dA = sb + st * STGB + tid * 16;
        const unsigned char* sA = gA + (size_t)c * ABYTES + tid * 16;
#pragma unroll
        for (int i = 0; i < 4; i++) cpa16(dA + i * 4096, sA + i * 4096);
        unsigned dB = sb + st * STGB + ABYTES + tid * 16;
        const unsigned char* sB = gB + (size_t)c * BBYTES + tid * 16;
#pragma unroll
        for (int i = 0; i < 8; i++) cpa16(dB + i * 4096, sB + i * 4096);
        asm volatile("cp.async.commit_group;" ::: "memory");
    };

    issue(0); issue(1); issue(2);

#pragma unroll 1
    for (int c = 0; c < NCHUNK; c++) {
        if (c + 2 <= NCHUNK - 1)      asm volatile("cp.async.wait_group 2;" ::: "memory");
        else if (c + 1 <= NCHUNK - 1) asm volatile("cp.async.wait_group 1;" ::: "memory");
        else                          asm volatile("cp.async.wait_group 0;" ::: "memory");
        __syncthreads();
        if (c + 3 < NCHUNK) issue(c + 3);

        const unsigned stA = sb + (c & (NSTG - 1)) * STGB;
        const unsigned stB = stA + ABYTES;
#pragma unroll
        for (int kk = 0; kk < 4; kk++) {
            unsigned af[4][4];
#pragma unroll
            for (int mi = 0; mi < 4; mi++)
                ldsm4(af[mi][0], af[mi][1], af[mi][2], af[mi][3],
                      stA + (rowA + mi * 16) * 128 + ((((unsigned)(kk * 2) + kgA) ^ sw) << 4));
#pragma unroll
            for (int nj = 0; nj < 4; nj++) {
                unsigned b0, b1, b2, b3;
                ldsm4(b0, b1, b2, b3,
                      stB + (rowB + nj * 16) * 128 + ((((unsigned)(kk * 2) + kgB) ^ sw) << 4));
#pragma unroll
                for (int mi = 0; mi < 4; mi++) {
                    mma16816(acc[mi][nj * 2],     af[mi], b0, b1);
                    mma16816(acc[mi][nj * 2 + 1], af[mi], b2, b3);
                }
            }
        }
    }

    // epilogue: per-row argmax with exact first-max tie-break
    const int brow  = blockIdx.x * MT + wm * 64 + (l >> 2);
    const int fbase = blockIdx.y * NT + wn * 64 + (l & 3) * 2;
#pragma unroll
    for (int mi = 0; mi < 4; mi++)
#pragma unroll
        for (int h = 0; h < 2; h++) {
            float best = -3.402823466e+38f;
            int bestf = fbase;
#pragma unroll
            for (int nj8 = 0; nj8 < 8; nj8++)
#pragma unroll
                for (int j = 0; j < 2; j++) {
                    float v = acc[mi][nj8][h * 2 + j];
                    int f = fbase + nj8 * 8 + j;   // ascending f, strict > keeps first max
                    if (v > best) { best = v; bestf = f; }
                }
            unsigned long long key =
                ((unsigned long long)ordf(best) << 32) | (unsigned)(~(unsigned)bestf);
            unsigned long long o;
            o = __shfl_down_sync(0xffffffffu, key, 2, 4); if (o > key) key = o;
            o = __shfl_down_sync(0xffffffffu, key, 1, 4); if (o > key) key = o;
            if ((l & 3) == 0) atomicMax(&g_amax[brow + mi * 16 + h * 8], key);
        }
}

// ---------------- per-row sparse update ----------------
__global__ __launch_bounds__(256) void k_upd(const float* __restrict__ x,
                                             const float* __restrict__ xs) {
    extern __shared__ float dsm[];
    float* rsm   = dsm;
    float* atoms = dsm + D_;

    __shared__ int   ilist[NMAX];
    __shared__ float wlist[NMAX];
    __shared__ float gsm[NMAX];
    __shared__ int   sh_n;
    __shared__ float sh_step;
    __shared__ float redn[8], redd[8];

    const int b = blockIdx.x;
    const int tid = threadIdx.x;

    int n = g_nnz[b];
    if (tid < n) {
        ilist[tid] = g_idx[b * NMAX + tid];
        wlist[tid] = g_w[b * NMAX + tid];
    }
    __syncthreads();
    if (tid == 0) {
        unsigned long long key = g_amax[b];
        int m = (int)(~(unsigned)key);
        bool found = false;
        for (int j = 0; j < n; j++)
            if (ilist[j] == m) { found = true; break; }
        if (!found) { ilist[n] = m; wlist[n] = 0.f; n++; }
        sh_n = n;
        g_amax[b] = 0ULL;
    }
    __syncthreads();
    n = sh_n;

    for (int v = tid; v < D_; v += 256) rsm[v] = g_resid[(size_t)b * D_ + v];
    for (int e = tid; e < n * D_; e += 256) {
        int j = e >> 10, v = e & (D_ - 1);
        atoms[j * D_ + v] = xs[(size_t)ilist[j] * D_ + v];
    }
    __syncthreads();

    const int wid = tid >> 5, lane = tid & 31;
    for (int j = wid; j < n; j += 8) {
        float s = 0.f;
        const float* a = atoms + j * D_;
        for (int v = lane; v < D_; v += 32) s += rsm[v] * a[v];
#pragma unroll
        for (int off = 16; off; off >>= 1) s += __shfl_down_sync(0xffffffffu, s, off);
        if (lane == 0) gsm[j] = s;
    }
    __syncthreads();

    float num = 0.f, den = 0.f;
    {
        const int v0 = tid * 4;
        float c0 = 0.f, c1 = 0.f, c2 = 0.f, c3 = 0.f;
        for (int j = 0; j < n; j++) {
            float g = gsm[j];
            const float* a = atoms + j * D_ + v0;
            c0 += g * a[0]; c1 += g * a[1]; c2 += g * a[2]; c3 += g * a[3];
        }
        num = c0 * rsm[v0] + c1 * rsm[v0 + 1] + c2 * rsm[v0 + 2] + c3 * rsm[v0 + 3];
        den = c0 * c0 + c1 * c1 + c2 * c2 + c3 * c3;
    }
#pragma unroll
    for (int off = 16; off; off >>= 1) {
        num += __shfl_down_sync(0xffffffffu, num, off);
        den += __shfl_down_sync(0xffffffffu, den, off);
    }
    if (lane == 0) { redn[wid] = num; redd[wid] = den; }
    __syncthreads();
    if (tid == 0) {
        float N = 0.f, De = 0.f;
        for (int w = 0; w < 8; w++) { N += redn[w]; De += redd[w]; }
        sh_step = N / fmaxf(De, 1e-3f);
    }
    __syncthreads();
    const float step = sh_step;

    if (tid < n) wlist[tid] = fmaxf(0.f, wlist[tid] + step * gsm[tid]);
    __syncthreads();

    for (int v = tid; v < D_; v += 256) {
        float r = x[(size_t)b * D_ + v];
        for (int j = 0; j < n; j++) r -= wlist[j] * atoms[j * D_ + v];
        g_resid[(size_t)b * D_ + v] = r;
        store_rcat(b, v, r);
    }

    if (tid == 0) {
        int nn = 0;
        for (int j = 0; j < n; j++)
            if (wlist[j] > 0.f) {
                g_idx[b * NMAX + nn] = ilist[j];
                g_w[b * NMAX + nn] = wlist[j];
                nn++;
            }
        g_nnz[b] = nn;
    }
}

// ---------------- finalize: top_k emulation, decode, loss ----------------
__global__ __launch_bounds__(256) void k_fin(const float* __restrict__ y,
                                             const float* __restrict__ xs,
                                             const float* __restrict__ ys,
                                             float* __restrict__ out) {
    const int b = blockIdx.x, tid = threadIdx.x;
    __shared__ float sw[L0];
    __shared__ int   si[L0];
    __shared__ int   sn;
    __shared__ float red[8];

    if (tid == 0) {
        int n = g_nnz[b];
        float w[NMAX]; int id[NMAX];
        for (int j = 0; j < n; j++) { w[j] = g_w[b * NMAX + j]; id[j] = g_idx[b * NMAX + j]; }
        for (int a = 1; a < n; a++) {
            float wv = w[a]; int iv = id[a]; int p = a - 1;
            while (p >= 0 && (w[p] < wv || (w[p] == wv && id[p] > iv))) {
                w[p + 1] = w[p]; id[p + 1] = id[p]; p--;
            }
            w[p + 1] = wv; id[p + 1] = iv;
        }
        for (int k = 0; k < n; k++) { sw[k] = w[k]; si[k] = id[k]; }
        int f = 0;
        for (int k = n; k < L0; k++) {
            for (;;) {
                bool inS = false;
                for (int j = 0; j < n; j++) if (id[j] == f) { inS = true; break; }
                if (!inS) break;
                f++;
            }
            si[k] = f; sw[k] = 0.f; f++;
        }
        sn = n;
    }
    __syncthreads();
    const int n = sn;

    const size_t OFF_I  = (size_t)B_ * L0;
    const size_t OFF_XR = 2 * (size_t)B_ * L0;
    const size_t OFF_YR = OFF_XR + (size_t)B_ * D_;
    const size_t OFF_L  = OFF_YR + (size_t)B_ * D_;

    if (tid < L0) {
        out[(size_t)b * L0 + tid] = sw[tid];
        out[OFF_I + (size_t)b * L0 + tid] = (float)si[tid];
    }

    float lsum = 0.f;
    for (int v = tid; v < D_; v += 256) {
        float xr = 0.f, yr = 0.f;
        for (int k = 0; k < n; k++) {
            float w = sw[k];
            size_t base = (size_t)si[k] * D_ + v;
            xr += w * xs[base];
            yr += w * ys[base];
        }
        out[OFF_XR + (size_t)b * D_ + v] = xr;
        out[OFF_YR + (size_t)b * D_ + v] = yr;
        float d = yr - y[(size_t)b * D_ + v];
        lsum += d * d;
    }
    const int wid = tid >> 5, lane = tid & 31;
#pragma unroll
    for (int off = 16; off; off >>= 1) lsum += __shfl_down_sync(0xffffffffu, lsum, off);
    if (lane == 0) red[wid] = lsum;
    __syncthreads();
    if (tid == 0) {
        float L = 0.f;
        for (int w = 0; w < 8; w++) L += red[w];
        out[OFF_L + b] = L;
    }
}

// ---------------- launch ----------------
extern "C" void kernel_launch(void* const* d_in, const int* in_sizes, int n_in,
                              void* d_out, int out_size) {
    const float* x  = (const float*)d_in[0];
    const float* y  = (const float*)d_in[1];
    const float* xs = (const float*)d_in[2];
    const float* ys = (const float*)d_in[3];
    float* out = (float*)d_out;

    cudaFuncSetAttribute(k_upd, cudaFuncAttributeMaxDynamicSharedMemorySize,
                         (1 + NMAX) * D_ * (int)sizeof(float));
    cudaFuncSetAttribute(k_gemm_mma, cudaFuncAttributeMaxDynamicSharedMemorySize,
                         NSTG * STGB);

    k_prep_xs<<<F_, 768>>>(xs);
    k_init<<<(B_ * D_ + 255) / 256, 256>>>(x);
    for (int t = 0; t < L0; t++) {
        k_gemm_mma<<<dim3(B_ / MT, F_ / NT), 256, NSTG * STGB>>>();
        k_upd<<<B_, 256, (1 + NMAX) * D_ * (int)sizeof(float)>>>(x, xs);
    }
    k_fin<<<B_, 256>>>(y, xs, ys, out);
}